// round 3
// baseline (speedup 1.0000x reference)
#include <cuda_runtime.h>

#define IMG 28
#define IMG2 784              // 28*28
#define VPI 196               // float4 vectors per image
#define IMGS_PER_BLK 4        // 196*4 = 784 threads per block

__global__ __launch_bounds__(VPI * IMGS_PER_BLK)
void sr_geom_kernel(const float4* __restrict__ x4,
                    const int*    __restrict__ t,
                    const float*  __restrict__ Wk,
                    const float*  __restrict__ bias,
                    float4* __restrict__ out4,
                    int n_img)
{
    const int tx  = threadIdx.x;                       // 0..195: vec within image
    const int img = blockIdx.x * IMGS_PER_BLK + threadIdx.y;
    if (img >= n_img) return;

    const int v = img * VPI + tx;                      // global float4 index

    const int row  = tx / 7;                           // const-div: 1 IMAD.HI
    const int col0 = (tx - row * 7) * 4;

    const float4 val = x4[v];
    float res[4] = {val.x, val.y, val.z, val.w};

    const int tv = __ldg(&t[img]);                     // L1-resident broadcast
    const int hi = tv * tv;
    const int lo = (tv >= 1) ? (tv - 1) * (tv - 1) : -1;

    const int dr  = row - 14;
    const int dr2 = dr * dr;

    #pragma unroll
    for (int k = 0; k < 4; ++k) {
        const int dc = col0 + k - 14;
        const int d2 = dr2 + dc * dc;
        if (d2 <= hi && d2 > lo) {                     // rare (~8% of pixels)
            const int col = col0 + k;
            const float* base = (const float*)x4 + (size_t)img * IMG2;
            float acc = __ldg(bias);
            #pragma unroll
            for (int ki = 0; ki < 3; ++ki) {
                const int r = row + ki - 1;
                if (r < 0 || r >= IMG) continue;
                #pragma unroll
                for (int kj = 0; kj < 3; ++kj) {
                    const int c = col + kj - 1;
                    if (c < 0 || c >= IMG) continue;
                    acc += base[r * IMG + c] * __ldg(&Wk[ki * 3 + kj]);
                }
            }
            res[k] += acc;
        }
    }

    out4[v] = make_float4(res[0], res[1], res[2], res[3]);
}

extern "C" void kernel_launch(void* const* d_in, const int* in_sizes, int n_in,
                              void* d_out, int out_size)
{
    const float4* x4   = (const float4*)d_in[0];  // [B,1,28,28] f32
    const int*    t    = (const int*)   d_in[1];  // [B] i32
    const float*  Wk   = (const float*) d_in[2];  // [1,1,3,3] f32
    const float*  bias = (const float*) d_in[3];  // [1] f32
    float4* out4 = (float4*)d_out;

    const int B = in_sizes[1];
    dim3 block(VPI, IMGS_PER_BLK);
    const int grid = (B + IMGS_PER_BLK - 1) / IMGS_PER_BLK;
    sr_geom_kernel<<<grid, block>>>(x4, t, Wk, bias, out4, B);
}

// round 4
// speedup vs baseline: 1.0976x; 1.0976x over previous
#include <cuda_runtime.h>

#define IMG 28
#define IMG2 784              // 28*28
#define VPI 196               // float4 vectors per image
#define THREADS 256

__device__ __forceinline__ void process_img(float4& v, int tv,
                                            int row, int col0, int dr2,
                                            const float* __restrict__ base,
                                            const float* __restrict__ Wk,
                                            const float* __restrict__ bias)
{
    const int hi = tv * tv;
    const int lo = (tv >= 1) ? (tv - 1) * (tv - 1) : -1;
    float* res = reinterpret_cast<float*>(&v);

    #pragma unroll
    for (int k = 0; k < 4; ++k) {
        const int dc = col0 + k - 14;
        const int d2 = dr2 + dc * dc;
        if (d2 <= hi && d2 > lo) {                 // rare (~8% of pixels)
            const int col = col0 + k;
            float acc = __ldg(bias);
            #pragma unroll
            for (int ki = 0; ki < 3; ++ki) {
                const int r = row + ki - 1;
                if (r < 0 || r >= IMG) continue;
                #pragma unroll
                for (int kj = 0; kj < 3; ++kj) {
                    const int c = col + kj - 1;
                    if (c < 0 || c >= IMG) continue;
                    acc += base[r * IMG + c] * __ldg(&Wk[ki * 3 + kj]);
                }
            }
            res[k] += acc;
        }
    }
}

__global__ __launch_bounds__(THREADS)
void sr_mlp4_kernel(const float4* __restrict__ x4,
                    const int4*   __restrict__ t4,
                    const float*  __restrict__ Wk,
                    const float*  __restrict__ bias,
                    float4* __restrict__ out4,
                    int nquad)
{
    const int u = blockIdx.x * THREADS + threadIdx.x;
    const int quad = u / VPI;                      // group of 4 images
    if (quad >= nquad) return;
    const int tx = u - quad * VPI;                 // 0..195: vec within image

    const int img0 = quad * 4;

    // ---- front-batched independent loads: MLP = 5 ----
    const int4 tv4 = __ldg(&t4[quad]);
    float4 v0 = x4[(size_t)(img0 + 0) * VPI + tx];
    float4 v1 = x4[(size_t)(img0 + 1) * VPI + tx];
    float4 v2 = x4[(size_t)(img0 + 2) * VPI + tx];
    float4 v3 = x4[(size_t)(img0 + 3) * VPI + tx];

    // ---- geometry once, shared by all 4 images ----
    const int row  = tx / 7;
    const int col0 = (tx - row * 7) * 4;
    const int dr   = row - 14;
    const int dr2  = dr * dr;

    const float* xf = (const float*)x4;

    process_img(v0, tv4.x, row, col0, dr2, xf + (size_t)(img0 + 0) * IMG2, Wk, bias);
    out4[(size_t)(img0 + 0) * VPI + tx] = v0;
    process_img(v1, tv4.y, row, col0, dr2, xf + (size_t)(img0 + 1) * IMG2, Wk, bias);
    out4[(size_t)(img0 + 1) * VPI + tx] = v1;
    process_img(v2, tv4.z, row, col0, dr2, xf + (size_t)(img0 + 2) * IMG2, Wk, bias);
    out4[(size_t)(img0 + 2) * VPI + tx] = v2;
    process_img(v3, tv4.w, row, col0, dr2, xf + (size_t)(img0 + 3) * IMG2, Wk, bias);
    out4[(size_t)(img0 + 3) * VPI + tx] = v3;
}

extern "C" void kernel_launch(void* const* d_in, const int* in_sizes, int n_in,
                              void* d_out, int out_size)
{
    const float4* x4   = (const float4*)d_in[0];  // [B,1,28,28] f32
    const int4*   t4   = (const int4*)  d_in[1];  // [B] i32, B % 4 == 0
    const float*  Wk   = (const float*) d_in[2];  // [1,1,3,3] f32
    const float*  bias = (const float*) d_in[3];  // [1] f32
    float4* out4 = (float4*)d_out;

    const int B = in_sizes[1];
    const int nquad = B / 4;                      // B = 65536 -> 16384
    const long total = (long)nquad * VPI;         // threads needed
    const int blocks = (int)((total + THREADS - 1) / THREADS);
    sr_mlp4_kernel<<<blocks, THREADS>>>(x4, t4, Wk, bias, out4, nquad);
}